// round 16
// baseline (speedup 1.0000x reference)
#include <cuda_runtime.h>
#include <math.h>

#define Bv 8
#define Cv 64
#define Hv 128
#define Wv 128
#define Ov 64
#define HWv (Hv*Wv)

typedef unsigned long long u64;

__device__ __forceinline__ u64 ffma2(u64 a, u64 b, u64 c) {
    u64 d;
    asm("fma.rn.f32x2 %0, %1, %2, %3;" : "=l"(d) : "l"(a), "l"(b), "l"(c));
    return d;
}
__device__ __forceinline__ float unpk_sum(u64 v) {
    unsigned lo, hi;
    asm("mov.b64 {%0, %1}, %2;" : "=r"(lo), "=r"(hi) : "l"(v));
    return __uint_as_float(lo) + __uint_as_float(hi);
}
__device__ __forceinline__ u64 pk2(float a, float b) {
    u64 r;
    asm("mov.b64 %0, {%1, %2};" : "=l"(r) : "f"(a), "f"(b));
    return r;
}

// scratch (__device__ globals; no allocation allowed)
__device__ float g_offset[Bv*18*HWv];   // (B,18,H,W)
__device__ float g_mask[Bv*9*HWv];      // (B,9,H,W)
__device__ float g_xt[(size_t)Bv*HWv*Cv]; // (B,H,W,C)
__device__ float g_whP[Cv*18*16];
__device__ float g_whS[Cv*18*16];       // wh shifted: whS[m]=wh[m-1], whS[0]=0
__device__ float g_wvP[Cv*18*16];
__device__ float g_wmP[Cv*9*12];
__device__ float g_wdT[Ov*576];         // [o][j], j = k*16 + c/4 (float4 granules)
__device__ float g_psum[Ov];
__device__ float g_psq[Ov];
__device__ float g_mean[Ov];
__device__ float g_rstd[Ov];

// ---------------------------------------------------------------------------
// weight packer (+ zero the fused BN accumulators each launch)
// ---------------------------------------------------------------------------
__global__ void pack_kernel(const float* __restrict__ wh, const float* __restrict__ wv,
                            const float* __restrict__ wm, const float* __restrict__ wd) {
    int idx = blockIdx.x*256 + threadIdx.x;
    if (blockIdx.x == 0 && threadIdx.x < Ov) {
        g_psum[threadIdx.x] = 0.f;
        g_psq[threadIdx.x]  = 0.f;
    }
    if (idx < 18432) {
        int c = idx/288, r = idx - c*288, o = r >> 4, k = r & 15;
        g_whP[idx] = (k < 15) ? wh[(o*Cv + c)*15 + k] : 0.f;
        g_wvP[idx] = (k < 15) ? wv[(o*Cv + c)*15 + k] : 0.f;
    } else if (idx < 36864) {
        int j = idx - 18432;
        int c = j/288, r = j - c*288, o = r >> 4, k = r & 15;
        g_whS[j] = (k >= 1) ? wh[(o*Cv + c)*15 + (k-1)] : 0.f;
    } else if (idx < 36864 + 6912) {
        int j = idx - 36864;
        int c = j/108, r = j - c*108, o = r/12, k = r - o*12;
        g_wmP[j] = (k < 9) ? wm[(o*Cv + c)*9 + k] : 0.f;
    } else if (idx < 36864 + 6912 + 36864) {
        int j = idx - 36864 - 6912;
        int o = j/576, r = j - o*576, k = r >> 6, c = r & 63;
        g_wdT[j] = wd[(o*Cv + c)*9 + k];
    }
}

// ---------------------------------------------------------------------------
// x (B,C,HW) -> xt (B,HW,C)
// ---------------------------------------------------------------------------
__global__ void transpose_kernel(const float* __restrict__ x) {
    __shared__ float t[32][33];
    int b = blockIdx.z;
    int hw0 = blockIdx.x * 32;
    int c0  = blockIdx.y * 32;
    int tx = threadIdx.x, ty = threadIdx.y;
    #pragma unroll
    for (int j = 0; j < 4; j++) {
        int c = c0 + ty + j*8;
        t[ty + j*8][tx] = x[((size_t)b*Cv + c)*HWv + hw0 + tx];
    }
    __syncthreads();
    #pragma unroll
    for (int j = 0; j < 4; j++) {
        int hw = hw0 + ty + j*8;
        g_xt[((size_t)b*HWv + hw)*Cv + c0 + tx] = t[tx][ty + j*8];
    }
}

// ---------------------------------------------------------------------------
// fused offset(18ch) + mask(9ch), 32x8 tile, 128 threads, 2 px/thread.
// FFMA2 v3: K-pair packing, weight pairs natural from padded layouts (no
// splats), a1 alignment via g_whS, 3-phase split (H/V/M) limits live packs.
// ---------------------------------------------------------------------------
__global__ void __launch_bounds__(128, 4) offmask_kernel(
    const float* __restrict__ x,
    const float* __restrict__ bh, const float* __restrict__ bv,
    const float* __restrict__ bm)
{
    __shared__ float tiles[2][22*47];
    int b  = blockIdx.z;
    int h0 = blockIdx.y * 8;
    int wb = blockIdx.x * 32;
    int tid = threadIdx.x;
    int tx = tid & 15, ty = tid >> 4;
    int h = h0 + ty;
    int w = wb + 2*tx;

    // encoded load slots: enc = (oob<<26) | (goff<<11) | sidx ; -1 = unused
    int enc[8];
    #pragma unroll
    for (int s = 0; s < 8; s++) {
        int i = tid + s*128;
        if (i < 22*46) {
            int r = i / 46, cc = i - r*46;
            int gh = h0 + r - 7, gw = wb + cc - 7;
            int si = r*47 + cc;
            if (gh >= 0 && gh < Hv && gw >= 0 && gw < Wv)
                enc[s] = ((gh*Wv + gw) << 11) | si;
            else
                enc[s] = (1 << 26) | si;
        } else enc[s] = -1;
    }

    float acc0[18], acc1[18], am0[9], am1[9];
    #pragma unroll
    for (int o = 0; o < 18; o++) { float bo = bh[o] + bv[o]; acc0[o] = bo; acc1[o] = bo; }
    #pragma unroll
    for (int o = 0; o < 9; o++)  { float bo = bm[o]; am0[o] = bo; am1[o] = bo; }

    const float* xb = x + (size_t)b*Cv*HWv;

    {
        const float* xc = xb;
        #pragma unroll
        for (int s = 0; s < 8; s++)
            if (enc[s] >= 0) {
                int si = enc[s] & 0x7FF;
                tiles[0][si] = (enc[s] & (1<<26)) ? 0.f : __ldg(xc + ((enc[s] >> 11) & 0x7FFF));
            }
    }

    for (int c = 0; c < Cv; c++) {
        __syncthreads();
        if (c + 1 < Cv) {
            const float* xc = xb + (c+1)*HWv;
            float* dst = tiles[(c+1) & 1];
            #pragma unroll
            for (int s = 0; s < 8; s++)
                if (enc[s] >= 0) {
                    int si = enc[s] & 0x7FF;
                    dst[si] = (enc[s] & (1<<26)) ? 0.f : __ldg(xc + ((enc[s] >> 11) & 0x7FFF));
                }
        }
        const float* tile = tiles[c & 1];

        // ---- phase H: horizontal conv (a0 via whP pairs, a1 via whS pairs) ----
        {
            u64 xp[8];
            const float* rp = tile + (ty+7)*47 + 2*tx;
            #pragma unroll
            for (int j = 0; j < 8; j++) xp[j] = pk2(rp[2*j], rp[2*j+1]);
            const ulonglong2* whE = (const ulonglong2*)(g_whP + c*288);
            const ulonglong2* whS = (const ulonglong2*)(g_whS + c*288);
            #pragma unroll
            for (int o = 0; o < 18; o++) {
                ulonglong2 e0 = whE[o*4+0], e1 = whE[o*4+1], e2 = whE[o*4+2], e3 = whE[o*4+3];
                u64 t0 = 0;
                t0 = ffma2(xp[0], e0.x, t0); t0 = ffma2(xp[1], e0.y, t0);
                t0 = ffma2(xp[2], e1.x, t0); t0 = ffma2(xp[3], e1.y, t0);
                t0 = ffma2(xp[4], e2.x, t0); t0 = ffma2(xp[5], e2.y, t0);
                t0 = ffma2(xp[6], e3.x, t0); t0 = ffma2(xp[7], e3.y, t0);
                acc0[o] += unpk_sum(t0);
                ulonglong2 s0 = whS[o*4+0], s1 = whS[o*4+1], s2 = whS[o*4+2], s3 = whS[o*4+3];
                u64 t1 = 0;
                t1 = ffma2(xp[0], s0.x, t1); t1 = ffma2(xp[1], s0.y, t1);
                t1 = ffma2(xp[2], s1.x, t1); t1 = ffma2(xp[3], s1.y, t1);
                t1 = ffma2(xp[4], s2.x, t1); t1 = ffma2(xp[5], s2.y, t1);
                t1 = ffma2(xp[6], s3.x, t1); t1 = ffma2(xp[7], s3.y, t1);
                acc1[o] += unpk_sum(t1);
            }
        }

        // ---- phase V: vertical conv (a0 via xcA pairs, a1 via xcB pairs) ----
        {
            u64 xva[8], xvb[8];
            #pragma unroll
            for (int j = 0; j < 7; j++) {
                xva[j] = pk2(tile[(ty+2*j)*47 + 2*tx + 7], tile[(ty+2*j+1)*47 + 2*tx + 7]);
                xvb[j] = pk2(tile[(ty+2*j)*47 + 2*tx + 8], tile[(ty+2*j+1)*47 + 2*tx + 8]);
            }
            xva[7] = pk2(tile[(ty+14)*47 + 2*tx + 7], 0.f);
            xvb[7] = pk2(tile[(ty+14)*47 + 2*tx + 8], 0.f);
            const ulonglong2* wvE = (const ulonglong2*)(g_wvP + c*288);
            #pragma unroll
            for (int o = 0; o < 18; o++) {
                ulonglong2 v0 = wvE[o*4+0], v1 = wvE[o*4+1], v2 = wvE[o*4+2], v3 = wvE[o*4+3];
                u64 t0 = 0;
                t0 = ffma2(xva[0], v0.x, t0); t0 = ffma2(xva[1], v0.y, t0);
                t0 = ffma2(xva[2], v1.x, t0); t0 = ffma2(xva[3], v1.y, t0);
                t0 = ffma2(xva[4], v2.x, t0); t0 = ffma2(xva[5], v2.y, t0);
                t0 = ffma2(xva[6], v3.x, t0); t0 = ffma2(xva[7], v3.y, t0);
                acc0[o] += unpk_sum(t0);
                u64 t1 = 0;
                t1 = ffma2(xvb[0], v0.x, t1); t1 = ffma2(xvb[1], v0.y, t1);
                t1 = ffma2(xvb[2], v1.x, t1); t1 = ffma2(xvb[3], v1.y, t1);
                t1 = ffma2(xvb[4], v2.x, t1); t1 = ffma2(xvb[5], v2.y, t1);
                t1 = ffma2(xvb[6], v3.x, t1); t1 = ffma2(xvb[7], v3.y, t1);
                acc1[o] += unpk_sum(t1);
            }
        }

        // ---- phase M: mask conv, K-pairs (5 ffma2 per pixel per o) ----
        {
            float xr6 = tile[(ty+7)*47 + 2*tx + 6];
            float xr7 = tile[(ty+7)*47 + 2*tx + 7];
            float xr8 = tile[(ty+7)*47 + 2*tx + 8];
            float xr9 = tile[(ty+7)*47 + 2*tx + 9];
            float xA6 = tile[(ty+6)*47 + 2*tx + 7];
            float xB6 = tile[(ty+6)*47 + 2*tx + 8];
            float xA8 = tile[(ty+8)*47 + 2*tx + 7];
            float xB8 = tile[(ty+8)*47 + 2*tx + 8];
            float t00 = tile[(ty+6)*47 + 2*tx + 6];
            float t01 = tile[(ty+6)*47 + 2*tx + 9];
            float t10 = tile[(ty+8)*47 + 2*tx + 6];
            float t11 = tile[(ty+8)*47 + 2*tx + 9];
            // m0 taps: t00 xA6 | xB6 xr6 | xr7 xr8 | t10 xA8 | xB8 0
            u64 p0a = pk2(t00, xA6), p0b = pk2(xB6, xr6), p0c = pk2(xr7, xr8);
            u64 p0d = pk2(t10, xA8), p0e = pk2(xB8, 0.f);
            // m1 taps: xA6 xB6 | t01 xr7 | xr8 xr9 | xA8 xB8 | t11 0
            u64 p1a = pk2(xA6, xB6), p1b = pk2(t01, xr7), p1c = pk2(xr8, xr9);
            u64 p1d = pk2(xA8, xB8), p1e = pk2(t11, 0.f);
            const ulonglong2* wmE = (const ulonglong2*)(g_wmP + c*108);
            #pragma unroll
            for (int o = 0; o < 9; o++) {
                ulonglong2 qA = wmE[o*3+0];         // (w0,w1),(w2,w3)
                ulonglong2 qB = wmE[o*3+1];         // (w4,w5),(w6,w7)
                u64 qC = ((const u64*)wmE)[o*6+4];  // (w8, w9=0)
                u64 t0 = 0;
                t0 = ffma2(p0a, qA.x, t0); t0 = ffma2(p0b, qA.y, t0);
                t0 = ffma2(p0c, qB.x, t0); t0 = ffma2(p0d, qB.y, t0);
                t0 = ffma2(p0e, qC,   t0);
                am0[o] += unpk_sum(t0);
                u64 t1 = 0;
                t1 = ffma2(p1a, qA.x, t1); t1 = ffma2(p1b, qA.y, t1);
                t1 = ffma2(p1c, qB.x, t1); t1 = ffma2(p1d, qB.y, t1);
                t1 = ffma2(p1e, qC,   t1);
                am1[o] += unpk_sum(t1);
            }
        }
    }

    #pragma unroll
    for (int o = 0; o < 18; o++) {
        float2 v; v.x = acc0[o]; v.y = acc1[o];
        *(float2*)&g_offset[((b*18 + o)*Hv + h)*Wv + w] = v;
    }
    #pragma unroll
    for (int o = 0; o < 9; o++) {
        float2 v;
        v.x = 1.f/(1.f + __expf(-am0[o]));
        v.y = 1.f/(1.f + __expf(-am1[o]));
        *(float2*)&g_mask[((b*9 + o)*Hv + h)*Wv + w] = v;
    }
}

// ---------------------------------------------------------------------------
// deform (R15 exact): software-pipelined, FFMA2 stage C, warp 8og x 4pg
// ---------------------------------------------------------------------------
#define SW_STRIDE 608
#define SW_FLOATS 38912
#define SS_STRIDE 580
#define OFF_SS   SW_FLOATS
#define OFF_RED  (OFF_SS + 16*SS_STRIDE)
#define OFF_SAC  (OFF_RED + 8*1088)
#define OFF_SAW  (OFF_SAC + 576)
#define SMEM_FLOATS (OFF_SAW + 576)     // 58048 floats = 232192 B

__device__ __forceinline__ int wrow_off(int o) {
    return o*SW_STRIDE + ((o >> 2) & 7)*4;
}

__global__ void __launch_bounds__(512, 1) deform_kernel(float* __restrict__ out) {
    extern __shared__ float smem[];
    float* sw   = smem;
    float* ss   = smem + OFF_SS;
    float* red  = smem + OFF_RED;
    int4*  sAc  = (int4*)(smem + OFF_SAC);
    float4* sAwf = (float4*)(smem + OFF_SAW);
    int tid = threadIdx.x;

    const float4* wt4 = (const float4*)g_wdT;
    for (int i = tid; i < 64*144; i += 512) {
        int o = i / 144, q = i - o*144;
        ((float4*)(sw + wrow_off(o)))[q] = wt4[i];
    }

    int h  = blockIdx.x >> 3;
    int w0 = (blockIdx.x & 7) << 4;

    int og = (tid & 7) | ((tid >> 2) & 8);
    int pg = (tid >> 3) & 3;
    int ks = tid >> 6;
    const ulonglong2* wp = (const ulonglong2*)(sw + wrow_off(og*4)) + ks*18;
    const ulonglong2* pp = (const ulonglong2*)(ss + (pg*4)*SS_STRIDE) + ks*18;

    float bn_s = 0.f, bn_q = 0.f;

    #define COMPUTE_A(bb) { \
        int p = tid / 9, k = tid - p*9; \
        int w = w0 + p; \
        int ky = k / 3, kx = k - ky*3; \
        float dy = g_offset[(((bb)*18 + 2*k    )*Hv + h)*Wv + w]; \
        float dx = g_offset[(((bb)*18 + 2*k + 1)*Hv + h)*Wv + w]; \
        float m  = g_mask  [(((bb)*9  + k      )*Hv + h)*Wv + w]; \
        float py = (float)(h + ky - 1) + dy; \
        float px = (float)(w + kx - 1) + dx; \
        float y0f = floorf(py), x0f = floorf(px); \
        float wy1 = py - y0f, wx1 = px - x0f; \
        float wy0 = 1.f - wy1, wx0 = 1.f - wx1; \
        int iy0 = (int)y0f, ix0 = (int)x0f; \
        bool vy0 = (iy0 >= 0)  && (iy0 < Hv); \
        bool vy1 = (iy0 >= -1) && (iy0 < Hv-1); \
        bool vx0 = (ix0 >= 0)  && (ix0 < Wv); \
        bool vx1 = (ix0 >= -1) && (ix0 < Wv-1); \
        int y0c = min(Hv-1, max(0, iy0)); \
        int y1c = min(Hv-1, max(0, iy0 + 1)); \
        int x0c = min(Wv-1, max(0, ix0)); \
        int x1c = min(Wv-1, max(0, ix0 + 1)); \
        sAc[tid] = make_int4(y0c*Wv + x0c, y0c*Wv + x1c, y1c*Wv + x0c, y1c*Wv + x1c); \
        sAwf[tid] = make_float4((vy0 && vx0) ? m*wy0*wx0 : 0.f, \
                                (vy0 && vx1) ? m*wy0*wx1 : 0.f, \
                                (vy1 && vx0) ? m*wy1*wx0 : 0.f, \
                                (vy1 && vx1) ? m*wy1*wx1 : 0.f); \
    }

    #define GATH(dst, IT, xb4p) { \
        int pk_ = (IT) >> 4, cq_ = (IT) & 15; \
        int4 cc = sAc[pk_]; \
        float4 wg = sAwf[pk_]; \
        float4 v00 = (xb4p)[cc.x*16 + cq_]; \
        float4 v01 = (xb4p)[cc.y*16 + cq_]; \
        float4 v10 = (xb4p)[cc.z*16 + cq_]; \
        float4 v11 = (xb4p)[cc.w*16 + cq_]; \
        dst.x = fmaf(wg.w, v11.x, fmaf(wg.z, v10.x, fmaf(wg.y, v01.x, wg.x*v00.x))); \
        dst.y = fmaf(wg.w, v11.y, fmaf(wg.z, v10.y, fmaf(wg.y, v01.y, wg.x*v00.y))); \
        dst.z = fmaf(wg.w, v11.z, fmaf(wg.z, v10.z, fmaf(wg.y, v01.z, wg.x*v00.z))); \
        dst.w = fmaf(wg.w, v11.w, fmaf(wg.z, v10.w, fmaf(wg.y, v01.w, wg.x*v00.w))); \
    }

    #define STSG(src, IT) { \
        int pk_ = (IT) >> 4, cq_ = (IT) & 15; \
        int p_ = pk_ / 9, k_ = pk_ - p_*9; \
        ((float4*)(ss + p_*SS_STRIDE))[k_*16 + cq_] = src; \
    }

    if (tid < 144) COMPUTE_A(0);
    __syncthreads();

    float4 g0, g1, g2, g3, g4;
    {
        const float4* xb4 = (const float4*)g_xt;
        GATH(g0, tid,        xb4);
        GATH(g1, 512 + tid,  xb4);
        GATH(g2, 1024 + tid, xb4);
        GATH(g3, 1536 + tid, xb4);
        if (tid < 256) GATH(g4, 2048 + tid, xb4);
    }
    __syncthreads();   // prologue GATH(0) reads complete before COMPUTE_A(1)

    for (int b = 0; b < Bv; b++) {
        STSG(g0, tid);
        STSG(g1, 512 + tid);
        STSG(g2, 1024 + tid);
        STSG(g3, 1536 + tid);
        if (tid < 256) STSG(g4, 2048 + tid);
        if (b + 1 < Bv && tid < 144) COMPUTE_A(b+1);
        __syncthreads();   // X: ss(b) + A(b+1) ready

        if (b + 1 < Bv) {
            const float4* xb4 = (const float4*)g_xt + (size_t)(b+1)*HWv*16;
            GATH(g0, tid,        xb4);
            GATH(g1, 512 + tid,  xb4);
            GATH(g2, 1024 + tid, xb4);
            GATH(g3, 1536 + tid, xb4);
            if (tid < 256) GATH(g4, 2048 + tid, xb4);
        }

        u64 A00=0,A01=0,A02=0,A03=0, A10=0,A11=0,A12=0,A13=0;
        u64 A20=0,A21=0,A22=0,A23=0, A30=0,A31=0,A32=0,A33=0;
        #pragma unroll
        for (int q = 0; q < 18; q++) {
            ulonglong2 qa = wp[q], qb = wp[q+152], qc = wp[q+304], qd = wp[q+456];
            ulonglong2 s0 = pp[q], s1 = pp[q+145], s2 = pp[q+290], s3 = pp[q+435];
            A00 = ffma2(qa.x, s0.x, A00); A00 = ffma2(qa.y, s0.y, A00);
            A01 = ffma2(qa.x, s1.x, A01); A01 = ffma2(qa.y, s1.y, A01);
            A02 = ffma2(qa.x, s2.x, A02); A02 = ffma2(qa.y, s2.y, A02);
            A03 = ffma2(qa.x, s3.x, A03); A03 = ffma2(qa.y, s3.y, A03);
            A10 = ffma2(qb.x, s0.x, A10); A10 = ffma2(qb.y, s0.y, A10);
            A11 = ffma2(qb.x, s1.x, A11); A11 = ffma2(qb.y, s1.y, A11);
            A12 = ffma2(qb.x, s2.x, A12); A12 = ffma2(qb.y, s2.y, A12);
            A13 = ffma2(qb.x, s3.x, A13); A13 = ffma2(qb.y, s3.y, A13);
            A20 = ffma2(qc.x, s0.x, A20); A20 = ffma2(qc.y, s0.y, A20);
            A21 = ffma2(qc.x, s1.x, A21); A21 = ffma2(qc.y, s1.y, A21);
            A22 = ffma2(qc.x, s2.x, A22); A22 = ffma2(qc.y, s2.y, A22);
            A23 = ffma2(qc.x, s3.x, A23); A23 = ffma2(qc.y, s3.y, A23);
            A30 = ffma2(qd.x, s0.x, A30); A30 = ffma2(qd.y, s0.y, A30);
            A31 = ffma2(qd.x, s1.x, A31); A31 = ffma2(qd.y, s1.y, A31);
            A32 = ffma2(qd.x, s2.x, A32); A32 = ffma2(qd.y, s2.y, A32);
            A33 = ffma2(qd.x, s3.x, A33); A33 = ffma2(qd.y, s3.y, A33);
        }
        {
            float4* rp = (float4*)red + ks*272 + og*17 + pg;
            rp[0]  = make_float4(unpk_sum(A00), unpk_sum(A01), unpk_sum(A02), unpk_sum(A03));
            rp[4]  = make_float4(unpk_sum(A10), unpk_sum(A11), unpk_sum(A12), unpk_sum(A13));
            rp[8]  = make_float4(unpk_sum(A20), unpk_sum(A21), unpk_sum(A22), unpk_sum(A23));
            rp[12] = make_float4(unpk_sum(A30), unpk_sum(A31), unpk_sum(A32), unpk_sum(A33));
        }
        __syncthreads();   // Y: red ready; all ss + sAc/sAw reads done

        if (tid < 256) {
            int o = tid >> 2, rpg = tid & 3;
            int base = (o >> 2)*17 + (o & 3)*4 + rpg;
            const float4* r4 = (const float4*)red;
            float4 v0 = r4[base];
            float4 v1 = r4[272  + base];
            float4 v2 = r4[544  + base];
            float4 v3 = r4[816  + base];
            float4 v4 = r4[1088 + base];
            float4 v5 = r4[1360 + base];
            float4 v6 = r4[1632 + base];
            float4 v7 = r4[1904 + base];
            float4 res;
            res.x = ((v0.x+v1.x)+(v2.x+v3.x)) + ((v4.x+v5.x)+(v6.x+v7.x));
            res.y = ((v0.y+v1.y)+(v2.y+v3.y)) + ((v4.y+v5.y)+(v6.y+v7.y));
            res.z = ((v0.z+v1.z)+(v2.z+v3.z)) + ((v4.z+v5.z)+(v6.z+v7.z));
            res.w = ((v0.w+v1.w)+(v2.w+v3.w)) + ((v4.w+v5.w)+(v6.w+v7.w));
            *(float4*)&out[((size_t)(b*Ov + o)*Hv + h)*Wv + w0 + rpg*4] = res;
            bn_s += (res.x + res.y) + (res.z + res.w);
            bn_q += fmaf(res.x,res.x, fmaf(res.y,res.y, fmaf(res.z,res.z, res.w*res.w)));
        }
    }

    if (tid < 256) {
        bn_s += __shfl_xor_sync(0xffffffff, bn_s, 1);
        bn_q += __shfl_xor_sync(0xffffffff, bn_q, 1);
        bn_s += __shfl_xor_sync(0xffffffff, bn_s, 2);
        bn_q += __shfl_xor_sync(0xffffffff, bn_q, 2);
        if ((tid & 3) == 0) {
            int o = tid >> 2;
            atomicAdd(&g_psum[o], bn_s);
            atomicAdd(&g_psq[o],  bn_q);
        }
    }
}

// ---------------------------------------------------------------------------
// BN stats (tiny) + normalize
// ---------------------------------------------------------------------------
__global__ void stats_kernel() {
    int c = threadIdx.x;
    const float inv = 1.f / (float)(Bv*HWv);
    float mean = g_psum[c] * inv;
    float var  = g_psq[c] * inv - mean*mean;
    g_mean[c] = mean;
    g_rstd[c] = rsqrtf(var + 1e-5f);
}

__global__ void bn_kernel(float* __restrict__ y,
                          const float* __restrict__ gamma,
                          const float* __restrict__ beta) {
    int idx = blockIdx.x*256 + threadIdx.x;
    if (idx >= Bv*Ov*HWv/4) return;
    int c = (idx >> 12) & 63;
    float a  = g_rstd[c] * gamma[c];
    float bb = fmaf(-g_mean[c], a, beta[c]);
    float4* p = (float4*)y;
    float4 v = p[idx];
    v.x = fmaxf(fmaf(v.x, a, bb), 0.f);
    v.y = fmaxf(fmaf(v.y, a, bb), 0.f);
    v.z = fmaxf(fmaf(v.z, a, bb), 0.f);
    v.w = fmaxf(fmaf(v.w, a, bb), 0.f);
    p[idx] = v;
}

// ---------------------------------------------------------------------------
extern "C" void kernel_launch(void* const* d_in, const int* in_sizes, int n_in,
                              void* d_out, int out_size) {
    const float* x     = (const float*)d_in[0];
    const float* wh    = (const float*)d_in[1];
    const float* bh    = (const float*)d_in[2];
    const float* wv    = (const float*)d_in[3];
    const float* bv    = (const float*)d_in[4];
    const float* wm    = (const float*)d_in[5];
    const float* bm    = (const float*)d_in[6];
    const float* wd    = (const float*)d_in[7];
    const float* gamma = (const float*)d_in[8];
    const float* beta  = (const float*)d_in[9];
    float* out = (float*)d_out;

    const int deform_smem = SMEM_FLOATS * 4;   // 232192 B
    cudaFuncSetAttribute(deform_kernel, cudaFuncAttributeMaxDynamicSharedMemorySize, deform_smem);

    pack_kernel<<<(36864 + 6912 + 36864 + 255)/256, 256>>>(wh, wv, wm, wd);
    transpose_kernel<<<dim3(HWv/32, Cv/32, Bv), dim3(32, 8)>>>(x);
    offmask_kernel<<<dim3(Wv/32, Hv/8, Bv), 128>>>(x, bh, bv, bm);
    deform_kernel<<<1024, 512, deform_smem>>>(out);
    stats_kernel<<<1, Ov>>>();
    bn_kernel<<<(Bv*Ov*HWv/4 + 255)/256, 256>>>(out, gamma, beta);
}

// round 17
// speedup vs baseline: 1.8769x; 1.8769x over previous
#include <cuda_runtime.h>
#include <math.h>

#define Bv 8
#define Cv 64
#define Hv 128
#define Wv 128
#define Ov 64
#define HWv (Hv*Wv)

typedef unsigned long long u64;

__device__ __forceinline__ u64 ffma2(u64 a, u64 b, u64 c) {
    u64 d;
    asm("fma.rn.f32x2 %0, %1, %2, %3;" : "=l"(d) : "l"(a), "l"(b), "l"(c));
    return d;
}
__device__ __forceinline__ float unpk_sum(u64 v) {
    unsigned lo, hi;
    asm("mov.b64 {%0, %1}, %2;" : "=r"(lo), "=r"(hi) : "l"(v));
    return __uint_as_float(lo) + __uint_as_float(hi);
}

// scratch (__device__ globals; no allocation allowed)
__device__ float g_offset[Bv*18*HWv];   // (B,18,H,W)
__device__ float g_mask[Bv*9*HWv];      // (B,9,H,W)
__device__ float g_xt[(size_t)Bv*HWv*Cv]; // (B,H,W,C)
__device__ float g_whP[Cv*18*16];
__device__ float g_wvP[Cv*18*16];
__device__ float g_wmP[Cv*9*12];
__device__ float g_wdT[Ov*576];         // [o][j], j = k*16 + c/4 (float4 granules)
__device__ float g_psum[Ov];
__device__ float g_psq[Ov];
__device__ float g_mean[Ov];
__device__ float g_rstd[Ov];

// ---------------------------------------------------------------------------
// weight packer (+ zero the fused BN accumulators each launch)
// ---------------------------------------------------------------------------
__global__ void pack_kernel(const float* __restrict__ wh, const float* __restrict__ wv,
                            const float* __restrict__ wm, const float* __restrict__ wd) {
    int idx = blockIdx.x*256 + threadIdx.x;
    if (blockIdx.x == 0 && threadIdx.x < Ov) {
        g_psum[threadIdx.x] = 0.f;
        g_psq[threadIdx.x]  = 0.f;
    }
    if (idx < 18432) {
        int c = idx/288, r = idx - c*288, o = r >> 4, k = r & 15;
        g_whP[idx] = (k < 15) ? wh[(o*Cv + c)*15 + k] : 0.f;
        g_wvP[idx] = (k < 15) ? wv[(o*Cv + c)*15 + k] : 0.f;
    } else if (idx < 18432 + 6912) {
        int j = idx - 18432;
        int c = j/108, r = j - c*108, o = r/12, k = r - o*12;
        g_wmP[j] = (k < 9) ? wm[(o*Cv + c)*9 + k] : 0.f;
    } else if (idx < 18432 + 6912 + 36864) {
        int j = idx - 18432 - 6912;
        int o = j/576, r = j - o*576, k = r >> 6, c = r & 63;
        g_wdT[j] = wd[(o*Cv + c)*9 + k];
    }
}

// ---------------------------------------------------------------------------
// x (B,C,HW) -> xt (B,HW,C)
// ---------------------------------------------------------------------------
__global__ void transpose_kernel(const float* __restrict__ x) {
    __shared__ float t[32][33];
    int b = blockIdx.z;
    int hw0 = blockIdx.x * 32;
    int c0  = blockIdx.y * 32;
    int tx = threadIdx.x, ty = threadIdx.y;
    #pragma unroll
    for (int j = 0; j < 4; j++) {
        int c = c0 + ty + j*8;
        t[ty + j*8][tx] = x[((size_t)b*Cv + c)*HWv + hw0 + tx];
    }
    __syncthreads();
    #pragma unroll
    for (int j = 0; j < 4; j++) {
        int hw = hw0 + ty + j*8;
        g_xt[((size_t)b*HWv + hw)*Cv + c0 + tx] = t[tx][ty + j*8];
    }
}

// ---------------------------------------------------------------------------
// fused offset(18ch) + mask(9ch): 64x8 tile, 256 threads, 2 px/thread
// (same inner code as the measured-best R15; wider tile -> -15% halo
// loads/pixel; occupancy 2 keeps a single wave: 256 blocks <= 296)
// ---------------------------------------------------------------------------
#define TW 64
#define TSTRIDE 79     // 64 + 14 halo = 78 cols, +1 pad
__global__ void __launch_bounds__(256, 2) offmask_kernel(
    const float* __restrict__ x,
    const float* __restrict__ bh, const float* __restrict__ bv,
    const float* __restrict__ bm)
{
    __shared__ float tiles[2][22*TSTRIDE];
    int b  = blockIdx.z;
    int h0 = blockIdx.y * 8;
    int wb = blockIdx.x * TW;
    int tid = threadIdx.x;
    int tx = tid & 31, ty = tid >> 5;
    int h = h0 + ty;
    int w = wb + 2*tx;

    int  soff[7], sidx[7];
    #pragma unroll
    for (int s = 0; s < 7; s++) {
        int i = tid + s*256;
        if (i < 22*78) {
            int r = i / 78, cc = i - r*78;
            int gh = h0 + r - 7, gw = wb + cc - 7;
            sidx[s] = r*TSTRIDE + cc;
            soff[s] = (gh >= 0 && gh < Hv && gw >= 0 && gw < Wv) ? gh*Wv + gw : -1;
        } else { sidx[s] = -1; soff[s] = -1; }
    }

    float acc0[18], acc1[18], am0[9], am1[9];
    #pragma unroll
    for (int o = 0; o < 18; o++) { float bo = bh[o] + bv[o]; acc0[o] = bo; acc1[o] = bo; }
    #pragma unroll
    for (int o = 0; o < 9; o++)  { float bo = bm[o]; am0[o] = bo; am1[o] = bo; }

    const float* xb = x + (size_t)b*Cv*HWv;

    {
        const float* xc = xb;
        #pragma unroll
        for (int s = 0; s < 7; s++)
            if (sidx[s] >= 0) tiles[0][sidx[s]] = (soff[s] >= 0) ? __ldg(xc + soff[s]) : 0.f;
    }

    for (int c = 0; c < Cv; c++) {
        __syncthreads();
        if (c + 1 < Cv) {
            const float* xc = xb + (c+1)*HWv;
            float* dst = tiles[(c+1) & 1];
            #pragma unroll
            for (int s = 0; s < 7; s++)
                if (sidx[s] >= 0) dst[sidx[s]] = (soff[s] >= 0) ? __ldg(xc + soff[s]) : 0.f;
        }
        const float* tile = tiles[c & 1];

        float xr[16];
        #pragma unroll
        for (int i = 0; i < 16; i++) xr[i] = tile[(ty+7)*TSTRIDE + 2*tx + i];
        float xcA[15], xcB[15];
        #pragma unroll
        for (int i = 0; i < 15; i++) {
            xcA[i] = tile[(ty+i)*TSTRIDE + 2*tx + 7];
            xcB[i] = tile[(ty+i)*TSTRIDE + 2*tx + 8];
        }
        float t00 = tile[(ty+6)*TSTRIDE + 2*tx + 6];
        float t01 = tile[(ty+6)*TSTRIDE + 2*tx + 9];
        float t10 = tile[(ty+8)*TSTRIDE + 2*tx + 6];
        float t11 = tile[(ty+8)*TSTRIDE + 2*tx + 9];

        const float4* whc = (const float4*)(g_whP + c*288);
        const float4* wvc = (const float4*)(g_wvP + c*288);
        const float4* wmc = (const float4*)(g_wmP + c*108);
        #pragma unroll
        for (int o = 0; o < 18; o++) {
            float4 q0 = whc[o*4+0], q1 = whc[o*4+1], q2 = whc[o*4+2], q3 = whc[o*4+3];
            float wkh[15] = {q0.x,q0.y,q0.z,q0.w, q1.x,q1.y,q1.z,q1.w,
                             q2.x,q2.y,q2.z,q2.w, q3.x,q3.y,q3.z};
            float a0 = acc0[o], a1 = acc1[o];
            #pragma unroll
            for (int k = 0; k < 15; k++) {
                a0 = fmaf(xr[k],   wkh[k], a0);
                a1 = fmaf(xr[k+1], wkh[k], a1);
            }
            float4 v0 = wvc[o*4+0], v1 = wvc[o*4+1], v2 = wvc[o*4+2], v3 = wvc[o*4+3];
            float wkv[15] = {v0.x,v0.y,v0.z,v0.w, v1.x,v1.y,v1.z,v1.w,
                             v2.x,v2.y,v2.z,v2.w, v3.x,v3.y,v3.z};
            #pragma unroll
            for (int k = 0; k < 15; k++) {
                a0 = fmaf(xcA[k], wkv[k], a0);
                a1 = fmaf(xcB[k], wkv[k], a1);
            }
            acc0[o] = a0; acc1[o] = a1;
        }
        #pragma unroll
        for (int o = 0; o < 9; o++) {
            float4 q0 = wmc[o*3], q1 = wmc[o*3+1], q2 = wmc[o*3+2];
            float m0 = am0[o], m1 = am1[o];
            m0 = fmaf(t00,    q0.x, m0);  m1 = fmaf(xcA[6], q0.x, m1);
            m0 = fmaf(xcA[6], q0.y, m0);  m1 = fmaf(xcB[6], q0.y, m1);
            m0 = fmaf(xcB[6], q0.z, m0);  m1 = fmaf(t01,    q0.z, m1);
            m0 = fmaf(xr[6],  q0.w, m0);  m1 = fmaf(xr[7],  q0.w, m1);
            m0 = fmaf(xr[7],  q1.x, m0);  m1 = fmaf(xr[8],  q1.x, m1);
            m0 = fmaf(xr[8],  q1.y, m0);  m1 = fmaf(xr[9],  q1.y, m1);
            m0 = fmaf(t10,    q1.z, m0);  m1 = fmaf(xcA[8], q1.z, m1);
            m0 = fmaf(xcA[8], q1.w, m0);  m1 = fmaf(xcB[8], q1.w, m1);
            m0 = fmaf(xcB[8], q2.x, m0);  m1 = fmaf(t11,    q2.x, m1);
            am0[o] = m0; am1[o] = m1;
        }
    }

    #pragma unroll
    for (int o = 0; o < 18; o++) {
        float2 v; v.x = acc0[o]; v.y = acc1[o];
        *(float2*)&g_offset[((b*18 + o)*Hv + h)*Wv + w] = v;
    }
    #pragma unroll
    for (int o = 0; o < 9; o++) {
        float2 v;
        v.x = 1.f/(1.f + __expf(-am0[o]));
        v.y = 1.f/(1.f + __expf(-am1[o]));
        *(float2*)&g_mask[((b*9 + o)*Hv + h)*Wv + w] = v;
    }
}

// ---------------------------------------------------------------------------
// deform (R15 exact): software-pipelined, FFMA2 stage C, warp 8og x 4pg
// ---------------------------------------------------------------------------
#define SW_STRIDE 608
#define SW_FLOATS 38912
#define SS_STRIDE 580
#define OFF_SS   SW_FLOATS
#define OFF_RED  (OFF_SS + 16*SS_STRIDE)
#define OFF_SAC  (OFF_RED + 8*1088)
#define OFF_SAW  (OFF_SAC + 576)
#define SMEM_FLOATS (OFF_SAW + 576)     // 58048 floats = 232192 B

__device__ __forceinline__ int wrow_off(int o) {
    return o*SW_STRIDE + ((o >> 2) & 7)*4;
}

__global__ void __launch_bounds__(512, 1) deform_kernel(float* __restrict__ out) {
    extern __shared__ float smem[];
    float* sw   = smem;
    float* ss   = smem + OFF_SS;
    float* red  = smem + OFF_RED;
    int4*  sAc  = (int4*)(smem + OFF_SAC);
    float4* sAwf = (float4*)(smem + OFF_SAW);
    int tid = threadIdx.x;

    const float4* wt4 = (const float4*)g_wdT;
    for (int i = tid; i < 64*144; i += 512) {
        int o = i / 144, q = i - o*144;
        ((float4*)(sw + wrow_off(o)))[q] = wt4[i];
    }

    int h  = blockIdx.x >> 3;
    int w0 = (blockIdx.x & 7) << 4;

    int og = (tid & 7) | ((tid >> 2) & 8);
    int pg = (tid >> 3) & 3;
    int ks = tid >> 6;
    const ulonglong2* wp = (const ulonglong2*)(sw + wrow_off(og*4)) + ks*18;
    const ulonglong2* pp = (const ulonglong2*)(ss + (pg*4)*SS_STRIDE) + ks*18;

    float bn_s = 0.f, bn_q = 0.f;

    #define COMPUTE_A(bb) { \
        int p = tid / 9, k = tid - p*9; \
        int w = w0 + p; \
        int ky = k / 3, kx = k - ky*3; \
        float dy = g_offset[(((bb)*18 + 2*k    )*Hv + h)*Wv + w]; \
        float dx = g_offset[(((bb)*18 + 2*k + 1)*Hv + h)*Wv + w]; \
        float m  = g_mask  [(((bb)*9  + k      )*Hv + h)*Wv + w]; \
        float py = (float)(h + ky - 1) + dy; \
        float px = (float)(w + kx - 1) + dx; \
        float y0f = floorf(py), x0f = floorf(px); \
        float wy1 = py - y0f, wx1 = px - x0f; \
        float wy0 = 1.f - wy1, wx0 = 1.f - wx1; \
        int iy0 = (int)y0f, ix0 = (int)x0f; \
        bool vy0 = (iy0 >= 0)  && (iy0 < Hv); \
        bool vy1 = (iy0 >= -1) && (iy0 < Hv-1); \
        bool vx0 = (ix0 >= 0)  && (ix0 < Wv); \
        bool vx1 = (ix0 >= -1) && (ix0 < Wv-1); \
        int y0c = min(Hv-1, max(0, iy0)); \
        int y1c = min(Hv-1, max(0, iy0 + 1)); \
        int x0c = min(Wv-1, max(0, ix0)); \
        int x1c = min(Wv-1, max(0, ix0 + 1)); \
        sAc[tid] = make_int4(y0c*Wv + x0c, y0c*Wv + x1c, y1c*Wv + x0c, y1c*Wv + x1c); \
        sAwf[tid] = make_float4((vy0 && vx0) ? m*wy0*wx0 : 0.f, \
                                (vy0 && vx1) ? m*wy0*wx1 : 0.f, \
                                (vy1 && vx0) ? m*wy1*wx0 : 0.f, \
                                (vy1 && vx1) ? m*wy1*wx1 : 0.f); \
    }

    #define GATH(dst, IT, xb4p) { \
        int pk_ = (IT) >> 4, cq_ = (IT) & 15; \
        int4 cc = sAc[pk_]; \
        float4 wg = sAwf[pk_]; \
        float4 v00 = (xb4p)[cc.x*16 + cq_]; \
        float4 v01 = (xb4p)[cc.y*16 + cq_]; \
        float4 v10 = (xb4p)[cc.z*16 + cq_]; \
        float4 v11 = (xb4p)[cc.w*16 + cq_]; \
        dst.x = fmaf(wg.w, v11.x, fmaf(wg.z, v10.x, fmaf(wg.y, v01.x, wg.x*v00.x))); \
        dst.y = fmaf(wg.w, v11.y, fmaf(wg.z, v10.y, fmaf(wg.y, v01.y, wg.x*v00.y))); \
        dst.z = fmaf(wg.w, v11.z, fmaf(wg.z, v10.z, fmaf(wg.y, v01.z, wg.x*v00.z))); \
        dst.w = fmaf(wg.w, v11.w, fmaf(wg.z, v10.w, fmaf(wg.y, v01.w, wg.x*v00.w))); \
    }

    #define STSG(src, IT) { \
        int pk_ = (IT) >> 4, cq_ = (IT) & 15; \
        int p_ = pk_ / 9, k_ = pk_ - p_*9; \
        ((float4*)(ss + p_*SS_STRIDE))[k_*16 + cq_] = src; \
    }

    if (tid < 144) COMPUTE_A(0);
    __syncthreads();

    float4 g0, g1, g2, g3, g4;
    {
        const float4* xb4 = (const float4*)g_xt;
        GATH(g0, tid,        xb4);
        GATH(g1, 512 + tid,  xb4);
        GATH(g2, 1024 + tid, xb4);
        GATH(g3, 1536 + tid, xb4);
        if (tid < 256) GATH(g4, 2048 + tid, xb4);
    }
    __syncthreads();   // prologue GATH(0) reads complete before COMPUTE_A(1)

    for (int b = 0; b < Bv; b++) {
        STSG(g0, tid);
        STSG(g1, 512 + tid);
        STSG(g2, 1024 + tid);
        STSG(g3, 1536 + tid);
        if (tid < 256) STSG(g4, 2048 + tid);
        if (b + 1 < Bv && tid < 144) COMPUTE_A(b+1);
        __syncthreads();   // X: ss(b) + A(b+1) ready

        if (b + 1 < Bv) {
            const float4* xb4 = (const float4*)g_xt + (size_t)(b+1)*HWv*16;
            GATH(g0, tid,        xb4);
            GATH(g1, 512 + tid,  xb4);
            GATH(g2, 1024 + tid, xb4);
            GATH(g3, 1536 + tid, xb4);
            if (tid < 256) GATH(g4, 2048 + tid, xb4);
        }

        u64 A00=0,A01=0,A02=0,A03=0, A10=0,A11=0,A12=0,A13=0;
        u64 A20=0,A21=0,A22=0,A23=0, A30=0,A31=0,A32=0,A33=0;
        #pragma unroll
        for (int q = 0; q < 18; q++) {
            ulonglong2 qa = wp[q], qb = wp[q+152], qc = wp[q+304], qd = wp[q+456];
            ulonglong2 s0 = pp[q], s1 = pp[q+145], s2 = pp[q+290], s3 = pp[q+435];
            A00 = ffma2(qa.x, s0.x, A00); A00 = ffma2(qa.y, s0.y, A00);
            A01 = ffma2(qa.x, s1.x, A01); A01 = ffma2(qa.y, s1.y, A01);
            A02 = ffma2(qa.x, s2.x, A02); A02 = ffma2(qa.y, s2.y, A02);
            A03 = ffma2(qa.x, s3.x, A03); A03 = ffma2(qa.y, s3.y, A03);
            A10 = ffma2(qb.x, s0.x, A10); A10 = ffma2(qb.y, s0.y, A10);
            A11 = ffma2(qb.x, s1.x, A11); A11 = ffma2(qb.y, s1.y, A11);
            A12 = ffma2(qb.x, s2.x, A12); A12 = ffma2(qb.y, s2.y, A12);
            A13 = ffma2(qb.x, s3.x, A13); A13 = ffma2(qb.y, s3.y, A13);
            A20 = ffma2(qc.x, s0.x, A20); A20 = ffma2(qc.y, s0.y, A20);
            A21 = ffma2(qc.x, s1.x, A21); A21 = ffma2(qc.y, s1.y, A21);
            A22 = ffma2(qc.x, s2.x, A22); A22 = ffma2(qc.y, s2.y, A22);
            A23 = ffma2(qc.x, s3.x, A23); A23 = ffma2(qc.y, s3.y, A23);
            A30 = ffma2(qd.x, s0.x, A30); A30 = ffma2(qd.y, s0.y, A30);
            A31 = ffma2(qd.x, s1.x, A31); A31 = ffma2(qd.y, s1.y, A31);
            A32 = ffma2(qd.x, s2.x, A32); A32 = ffma2(qd.y, s2.y, A32);
            A33 = ffma2(qd.x, s3.x, A33); A33 = ffma2(qd.y, s3.y, A33);
        }
        {
            float4* rp = (float4*)red + ks*272 + og*17 + pg;
            rp[0]  = make_float4(unpk_sum(A00), unpk_sum(A01), unpk_sum(A02), unpk_sum(A03));
            rp[4]  = make_float4(unpk_sum(A10), unpk_sum(A11), unpk_sum(A12), unpk_sum(A13));
            rp[8]  = make_float4(unpk_sum(A20), unpk_sum(A21), unpk_sum(A22), unpk_sum(A23));
            rp[12] = make_float4(unpk_sum(A30), unpk_sum(A31), unpk_sum(A32), unpk_sum(A33));
        }
        __syncthreads();   // Y: red ready; all ss + sAc/sAw reads done

        if (tid < 256) {
            int o = tid >> 2, rpg = tid & 3;
            int base = (o >> 2)*17 + (o & 3)*4 + rpg;
            const float4* r4 = (const float4*)red;
            float4 v0 = r4[base];
            float4 v1 = r4[272  + base];
            float4 v2 = r4[544  + base];
            float4 v3 = r4[816  + base];
            float4 v4 = r4[1088 + base];
            float4 v5 = r4[1360 + base];
            float4 v6 = r4[1632 + base];
            float4 v7 = r4[1904 + base];
            float4 res;
            res.x = ((v0.x+v1.x)+(v2.x+v3.x)) + ((v4.x+v5.x)+(v6.x+v7.x));
            res.y = ((v0.y+v1.y)+(v2.y+v3.y)) + ((v4.y+v5.y)+(v6.y+v7.y));
            res.z = ((v0.z+v1.z)+(v2.z+v3.z)) + ((v4.z+v5.z)+(v6.z+v7.z));
            res.w = ((v0.w+v1.w)+(v2.w+v3.w)) + ((v4.w+v5.w)+(v6.w+v7.w));
            *(float4*)&out[((size_t)(b*Ov + o)*Hv + h)*Wv + w0 + rpg*4] = res;
            bn_s += (res.x + res.y) + (res.z + res.w);
            bn_q += fmaf(res.x,res.x, fmaf(res.y,res.y, fmaf(res.z,res.z, res.w*res.w)));
        }
    }

    if (tid < 256) {
        bn_s += __shfl_xor_sync(0xffffffff, bn_s, 1);
        bn_q += __shfl_xor_sync(0xffffffff, bn_q, 1);
        bn_s += __shfl_xor_sync(0xffffffff, bn_s, 2);
        bn_q += __shfl_xor_sync(0xffffffff, bn_q, 2);
        if ((tid & 3) == 0) {
            int o = tid >> 2;
            atomicAdd(&g_psum[o], bn_s);
            atomicAdd(&g_psq[o],  bn_q);
        }
    }
}

// ---------------------------------------------------------------------------
// BN stats (tiny) + normalize
// ---------------------------------------------------------------------------
__global__ void stats_kernel() {
    int c = threadIdx.x;
    const float inv = 1.f / (float)(Bv*HWv);
    float mean = g_psum[c] * inv;
    float var  = g_psq[c] * inv - mean*mean;
    g_mean[c] = mean;
    g_rstd[c] = rsqrtf(var + 1e-5f);
}

__global__ void bn_kernel(float* __restrict__ y,
                          const float* __restrict__ gamma,
                          const float* __restrict__ beta) {
    int idx = blockIdx.x*256 + threadIdx.x;
    if (idx >= Bv*Ov*HWv/4) return;
    int c = (idx >> 12) & 63;
    float a  = g_rstd[c] * gamma[c];
    float bb = fmaf(-g_mean[c], a, beta[c]);
    float4* p = (float4*)y;
    float4 v = p[idx];
    v.x = fmaxf(fmaf(v.x, a, bb), 0.f);
    v.y = fmaxf(fmaf(v.y, a, bb), 0.f);
    v.z = fmaxf(fmaf(v.z, a, bb), 0.f);
    v.w = fmaxf(fmaf(v.w, a, bb), 0.f);
    p[idx] = v;
}

// ---------------------------------------------------------------------------
extern "C" void kernel_launch(void* const* d_in, const int* in_sizes, int n_in,
                              void* d_out, int out_size) {
    const float* x     = (const float*)d_in[0];
    const float* wh    = (const float*)d_in[1];
    const float* bh    = (const float*)d_in[2];
    const float* wv    = (const float*)d_in[3];
    const float* bv    = (const float*)d_in[4];
    const float* wm    = (const float*)d_in[5];
    const float* bm    = (const float*)d_in[6];
    const float* wd    = (const float*)d_in[7];
    const float* gamma = (const float*)d_in[8];
    const float* beta  = (const float*)d_in[9];
    float* out = (float*)d_out;

    const int deform_smem = SMEM_FLOATS * 4;   // 232192 B
    cudaFuncSetAttribute(deform_kernel, cudaFuncAttributeMaxDynamicSharedMemorySize, deform_smem);

    pack_kernel<<<(18432 + 6912 + 36864 + 255)/256, 256>>>(wh, wv, wm, wd);
    transpose_kernel<<<dim3(HWv/32, Cv/32, Bv), dim3(32, 8)>>>(x);
    offmask_kernel<<<dim3(Wv/TW, Hv/8, Bv), 256>>>(x, bh, bv, bm);
    deform_kernel<<<1024, 512, deform_smem>>>(out);
    stats_kernel<<<1, Ov>>>();
    bn_kernel<<<(Bv*Ov*HWv/4 + 255)/256, 256>>>(out, gamma, beta);
}